// round 9
// baseline (speedup 1.0000x reference)
#include <cuda_runtime.h>
#include <cuda_bf16.h>
#include <math.h>
#include <cstdint>

// ---------------------------------------------------------------------------
// StatefulCausalAttention  (B=1, H=16, T=2304=128+2048+128, D=1024, dk=dv=64)
// R9: stage loads via cp.async.bulk + mbarrier (1-2 bulk copies per stage vs
//     1000+ cp.async). K/V stored with gmem-baked XOR swizzle (conflict-free
//     unpadded LDS.64); V tile-blocked [h][jt][dv][64]. Attention retiled to
//     m32 warp tiles (128 thr, 4 warps, 2 CTA/SM).
// ---------------------------------------------------------------------------

#define T_TOT 2304
#define D_IN  1024
#define NH    16

// projection outputs
__device__ float g_Qf[NH * T_TOT * 64];        // natural row-major (attn LDG)
__device__ float g_Kf[NH * T_TOT * 64];        // row-major, f2-swizzled cols
__device__ float g_VTf[NH * 36 * 64 * 64];     // [h][jt][dv][64], swizzled

// frag-shuffled tf32 operands for projection
__device__ float g_Xf[144 * 64 * 2 * 32 * 4];
__device__ float g_Wf[6 * 16 * 64 * 8 * 32 * 4];

// ============================ helpers ======================================
__device__ __forceinline__ float ex2f_fast(float x) {
    float y; asm("ex2.approx.f32 %0, %1;" : "=f"(y) : "f"(x)); return y;
}
__device__ __forceinline__ void mma1688t(float* c, uint32_t a0, uint32_t a1,
                                         uint32_t a2, uint32_t a3,
                                         uint32_t b0, uint32_t b1) {
    asm("mma.sync.aligned.m16n8k8.row.col.f32.tf32.tf32.f32 "
        "{%0,%1,%2,%3}, {%4,%5,%6,%7}, {%8,%9}, {%0,%1,%2,%3};"
        : "+f"(c[0]), "+f"(c[1]), "+f"(c[2]), "+f"(c[3])
        : "r"(a0), "r"(a1), "r"(a2), "r"(a3), "r"(b0), "r"(b1));
}
__device__ __forceinline__ uint32_t to_tf32(float f) {
    uint32_t u; asm("cvt.rna.tf32.f32 %0, %1;" : "=r"(u) : "f"(f)); return u;
}
__device__ __forceinline__ uint32_t smem_u32(const void* p) {
    uint32_t a;
    asm("{ .reg .u64 t; cvta.to.shared.u64 t, %1; cvt.u32.u64 %0, t; }" : "=r"(a) : "l"(p));
    return a;
}
#define MBAR_INIT(a, n) \
    asm volatile("mbarrier.init.shared.b64 [%0], %1;" :: "r"((uint32_t)(a)), "r"((uint32_t)(n)) : "memory")
#define MBAR_EXPECT_TX(a, tx) \
    asm volatile("mbarrier.arrive.expect_tx.shared.b64 _, [%0], %1;" \
        :: "r"((uint32_t)(a)), "r"((uint32_t)(tx)) : "memory")
#define MBAR_WAIT(a, par) do {                                                      \
    uint32_t _m = (uint32_t)(a); uint32_t _p = (uint32_t)(par); uint32_t _d;        \
    asm volatile("{ .reg .pred p; mbarrier.try_wait.parity.acquire.cta.shared::cta.b64 p, [%1], %2; selp.b32 %0, 1, 0, p; }" \
        : "=r"(_d) : "r"(_m), "r"(_p) : "memory");                                  \
    if (!_d) {                                                                       \
        asm volatile("{ .reg .pred P1;\nWL_%=:\n mbarrier.try_wait.parity.acquire.cta.shared::cta.b64 P1, [%0], %1, 0x989680;\n @P1 bra.uni WD_%=;\n bra.uni WL_%=;\nWD_%=:\n}" \
            :: "r"(_m), "r"(_p) : "memory");                                        \
    } } while (0)
#define BULK_CP(dst, src, bytes, mbar) \
    asm volatile("cp.async.bulk.shared::cluster.global.mbarrier::complete_tx::bytes [%0], [%1], %2, [%3];" \
        :: "r"((uint32_t)(dst)), "l"(src), "r"((uint32_t)(bytes)), "r"((uint32_t)(mbar)) : "memory")

// ============================ prep: X + W -> frag order (merged) ===========
__global__ __launch_bounds__(256) void conv_kernel(
    const float* __restrict__ x,
    const float* __restrict__ Wq,  const float* __restrict__ Wk,  const float* __restrict__ Wv,
    const float* __restrict__ Wqs, const float* __restrict__ Wks, const float* __restrict__ Wvs)
{
    const int bid = blockIdx.x;
    if (bid < 144) {
        const int strip = bid;
        for (int i = threadIdx.x; i < 4096; i += 256) {
            int c = i >> 6, rest = i & 63;
            int t = rest >> 5, ln = rest & 31;
            int g = ln >> 2, q = ln & 3;
            const float* xr = x + (size_t)(strip * 16 + t * 8 + g) * D_IN + c * 16;
            uint4 v;
            v.x = to_tf32(xr[q]);
            v.y = to_tf32(xr[8 + q]);
            v.z = to_tf32(xr[4 + q]);
            v.w = to_tf32(xr[12 + q]);
            ((uint4*)g_Xf)[(size_t)(strip * 64 + c) * 64 + rest] = v;
        }
    } else {
        const int wb = bid - 144;          // 0..383
        const int cb = (wb & 3) * 16;
        const int mh = wb >> 2;            // 0..95
        const int mat = mh >> 4, h = mh & 15;
        const float* W;
        switch (mat) {
            case 0: W = Wq;  break; case 1: W = Wqs; break;
            case 2: W = Wk;  break; case 3: W = Wks; break;
            case 4: W = Wv;  break; default: W = Wvs; break;
        }
        W += (size_t)h * D_IN * 64;
        const int tid = threadIdx.x;
        const int ntl = tid >> 5, ln = tid & 31;
        const int g = ln >> 2, r = ln & 3;
        const int n = ntl * 8 + g;
#pragma unroll 4
        for (int ci = 0; ci < 16; ++ci) {
            const int c = cb + ci, k0 = c * 16;
            uint4 v;
            v.x = to_tf32(W[(size_t)(k0 + r) * 64 + n]);
            v.y = to_tf32(W[(size_t)(k0 + 8 + r) * 64 + n]);
            v.z = to_tf32(W[(size_t)(k0 + 4 + r) * 64 + n]);
            v.w = to_tf32(W[(size_t)(k0 + 12 + r) * 64 + n]);
            ((uint4*)g_Wf)[((size_t)(mat * 16 + h) * 64 + c) * 256 + tid] = v;
        }
    }
}

// ============================ projection (tf32 mma, 512 thr) ===============
// 4-stage ring via cp.async.bulk + mbarrier. Stage s at s*20480:
// A 512 uint4 (8KB), B 768 uint4 (12KB). nrm @81920; mbars @83456.
#define PROJ_SMEM 83488

__global__ __launch_bounds__(512, 1) void proj_kernel(const float* __restrict__ sf)
{
    extern __shared__ char smc[];
    float* nrm = (float*)(smc + 81920);
    const uint32_t sb = smem_u32(smc);
    const uint32_t mbp = sb + 83456;
    const int h  = blockIdx.x;
    const int by = blockIdx.y;
    const int state = (by == 0 || by == 17) ? 1 : 0;
    const int tid = threadIdx.x, warp = tid >> 5, lane = tid & 31;
    const int mi = warp >> 2, ni = warp & 3;
    const int g = lane >> 2, qq = lane & 3;
    const int strip0 = by * 8;

    for (int i = tid; i < 384; i += 512) nrm[i] = 0.f;
    if (tid == 0) {
#pragma unroll
        for (int s = 0; s < 4; ++s) MBAR_INIT(mbp + s * 8, 1);
    }
    __syncthreads();

    float acc[2][6][4];
#pragma unroll
    for (int st = 0; st < 2; ++st)
#pragma unroll
        for (int nt = 0; nt < 6; ++nt)
#pragma unroll
            for (int e = 0; e < 4; ++e) acc[st][nt][e] = 0.f;

    auto issue_stage = [&](int c) {
        if (tid == 0) {
            const uint32_t m  = mbp + (c & 3) * 8;
            const uint32_t sa = sb + (c & 3) * 20480;
            MBAR_EXPECT_TX(m, 20480);
#pragma unroll
            for (int s = 0; s < 8; ++s) {
                const float* src = g_Xf + ((size_t)((strip0 + s) * 64 + c)) * 256;
                BULK_CP(sa + s * 1024, src, 1024, m);
            }
#pragma unroll
            for (int t = 0; t < 3; ++t) {
                int mat = t * 2 + state;
                const float* src = g_Wf + ((size_t)(mat * 16 + h) * 64 + c) * 1024;
                BULK_CP(sa + 8192 + t * 4096, src, 4096, m);
            }
        }
    };

    issue_stage(0); issue_stage(1); issue_stage(2);

    for (int c = 0; c < 64; ++c) {
        MBAR_WAIT(mbp + (c & 3) * 8, (c >> 2) & 1);
        const char* sa = smc + (c & 3) * 20480;

        uint4 Af[2][2], Bf[6];
#pragma unroll
        for (int st = 0; st < 2; ++st)
#pragma unroll
            for (int t = 0; t < 2; ++t)
                Af[st][t] = *(const uint4*)(sa + (((mi * 2 + st) * 2 + t) * 32 + lane) * 16);
#pragma unroll
        for (int nt = 0; nt < 6; ++nt)
            Bf[nt] = *(const uint4*)(sa + 8192 + ((ni * 6 + nt) * 32 + lane) * 16);

#pragma unroll
        for (int s = 0; s < 2; ++s) {
#pragma unroll
            for (int st = 0; st < 2; ++st) {
                uint32_t a0 = s ? Af[st][0].y : Af[st][0].x;
                uint32_t a1 = s ? Af[st][1].y : Af[st][1].x;
                uint32_t a2 = s ? Af[st][0].w : Af[st][0].z;
                uint32_t a3 = s ? Af[st][1].w : Af[st][1].z;
#pragma unroll
                for (int nt = 0; nt < 6; ++nt) {
                    uint32_t b0 = s ? Bf[nt].y : Bf[nt].x;
                    uint32_t b1 = s ? Bf[nt].w : Bf[nt].z;
                    mma1688t(acc[st][nt], a0, a1, a2, a3, b0, b1);
                }
            }
        }
        __syncthreads();
        if (c + 3 < 64) issue_stage(c + 3);
    }

    // ---- norm partials ----
#pragma unroll
    for (int st = 0; st < 2; ++st) {
#pragma unroll
        for (int nt = 0; nt < 6; ++nt) {
            int mat = (ni * 6 + nt) >> 3;
            int rl0 = (mi * 2 + st) * 16 + g;
            atomicAdd(&nrm[mat * 128 + rl0],
                      acc[st][nt][0] * acc[st][nt][0] + acc[st][nt][1] * acc[st][nt][1]);
            atomicAdd(&nrm[mat * 128 + rl0 + 8],
                      acc[st][nt][2] * acc[st][nt][2] + acc[st][nt][3] * acc[st][nt][3]);
        }
    }
    __syncthreads();

    // ---- scale + store ----
    const float qs = sf[h] * 1.44269504088896340736f;
#pragma unroll
    for (int st = 0; st < 2; ++st) {
        const int rl0 = (mi * 2 + st) * 16 + g;
        const int rg0 = by * 128 + rl0;
#pragma unroll
        for (int nt = 0; nt < 6; ++nt) {
            const int ntg = ni * 6 + nt;
            const int mat = ntg >> 3;
            const int ntl = ntg & 7;
            const float mult = (mat == 0) ? qs : 1.0f;
            float inv0 = mult / fmaxf(sqrtf(nrm[mat * 128 + rl0]),     1e-12f);
            float inv1 = mult / fmaxf(sqrtf(nrm[mat * 128 + rl0 + 8]), 1e-12f);
            float v0 = acc[st][nt][0] * inv0, v1 = acc[st][nt][1] * inv0;
            float v2 = acc[st][nt][2] * inv1, v3 = acc[st][nt][3] * inv1;
            const int col = ntl * 8 + qq * 2;
            if (mat == 0) {
                float* dst = g_Qf + (size_t)h * T_TOT * 64;
                *(uint2*)(dst + (size_t)(rg0    ) * 64 + col) =
                    make_uint2(to_tf32(v0), to_tf32(v1));
                *(uint2*)(dst + (size_t)(rg0 + 8) * 64 + col) =
                    make_uint2(to_tf32(v2), to_tf32(v3));
            } else if (mat == 1) {
                // K: f2-swizzled columns (f2 ^= (row&3)<<2); rows rg0, rg0+8 share row&3
                float* dst = g_Kf + (size_t)h * T_TOT * 64;
                int f2 = (ntl * 4 + qq) ^ ((rg0 & 3) << 2);
                *(uint2*)(dst + (size_t)(rg0    ) * 64 + f2 * 2) =
                    make_uint2(to_tf32(v0), to_tf32(v1));
                *(uint2*)(dst + (size_t)(rg0 + 8) * 64 + f2 * 2) =
                    make_uint2(to_tf32(v2), to_tf32(v3));
            } else {
                // V: tile-blocked [h][jt][dv][64], word-swizzled tt ^= (dv&3)<<3
                float vv[4] = {v0, v1, v2, v3};
#pragma unroll
                for (int e = 0; e < 4; ++e) {
                    int cc = col + (e & 1);            // dv
                    int rr = rg0 + (e >> 1) * 8;       // t
                    int jt = rr >> 6, tt = rr & 63;
                    size_t idx = (((size_t)(h * 36 + jt) * 64 + cc) * 64)
                                 + (tt ^ ((cc & 3) << 3));
                    g_VTf[idx] = __uint_as_float(to_tf32(vv[e]));
                }
            }
        }
    }
}

// ============================ attention v5 =================================
// 128 threads = 4 warps x m32 (2 strips of m16); kv-tile 64; 2 CTA/SM;
// snake schedule. Stages: K 16KB @0, V 16KB @16384; stage1 @32768.
// mbarriers @65536. Stage fill = 2 cp.async.bulk by thread 0.
#define ATTN_SMEM (65536 + 64)

__global__ __launch_bounds__(128, 2) void attn_kernel(float* __restrict__ out)
{
    extern __shared__ char smc[];
    const uint32_t sb = smem_u32(smc);
    const uint32_t mb = sb + 65536;
    const int L = blockIdx.x;
    const int r = (L < 152) ? L : 439 - L;
    const int h  = r & 15;
    const int it = 17 - (r >> 4);
    const int rb = it * 128;
    const int tid = threadIdx.x;
    const int warp = tid >> 5, lane = tid & 31;
    const int g = lane >> 2, q = lane & 3;
    const int rgs0 = rb + warp * 32 + g;      // strip 0 rows: rgs0, rgs0+8
    const int rgs1 = rgs0 + 16;               // strip 1 rows: rgs1, rgs1+8

    if (tid == 0) { MBAR_INIT(mb, 1); MBAR_INIT(mb + 8, 1); }
    __syncthreads();

    // ---- Q fragments (k-lane q <-> logical k = 2q,2q+1) ----
    uint32_t qf[8][2][4];
    {
        const float* Q0 = g_Qf + ((size_t)h * T_TOT + rgs0) * 64;
        const float* Q1 = g_Qf + ((size_t)h * T_TOT + rgs1) * 64;
#pragma unroll
        for (int ks = 0; ks < 8; ++ks) {
            float2 lo0 = *(const float2*)&Q0[ks * 8 + 2 * q];
            float2 hi0 = *(const float2*)&Q0[8 * 64 + ks * 8 + 2 * q];
            qf[ks][0][0] = __float_as_uint(lo0.x);
            qf[ks][0][1] = __float_as_uint(hi0.x);
            qf[ks][0][2] = __float_as_uint(lo0.y);
            qf[ks][0][3] = __float_as_uint(hi0.y);
            float2 lo1 = *(const float2*)&Q1[ks * 8 + 2 * q];
            float2 hi1 = *(const float2*)&Q1[8 * 64 + ks * 8 + 2 * q];
            qf[ks][1][0] = __float_as_uint(lo1.x);
            qf[ks][1][1] = __float_as_uint(hi1.x);
            qf[ks][1][2] = __float_as_uint(lo1.y);
            qf[ks][1][3] = __float_as_uint(hi1.y);
        }
    }

    float o[2][8][4];
#pragma unroll
    for (int s2 = 0; s2 < 2; ++s2)
#pragma unroll
        for (int j = 0; j < 8; ++j)
#pragma unroll
            for (int e = 0; e < 4; ++e) o[s2][j][e] = 0.f;
    float lacc[2][2] = {{0.f, 0.f}, {0.f, 0.f}};

    const int jt0 = (it == 17) ? 2 : 0;
    const int jt1 = 2 * it + 1;

    auto issue_stage = [&](int jt, int buf) {
        if (tid == 0) {
            const uint32_t m = mb + buf * 8;
            const uint32_t stb = sb + buf * 32768;
            MBAR_EXPECT_TX(m, 32768);
            const float* ksrc = g_Kf + ((size_t)h * T_TOT + jt * 64) * 64;
            const float* vsrc = g_VTf + (size_t)(h * 36 + jt) * 4096;
            BULK_CP(stb, ksrc, 16384, m);
            BULK_CP(stb + 16384, vsrc, 16384, m);
        }
    };

    issue_stage(jt0, 0);

    for (int jt = jt0; jt <= jt1; ++jt) {
        const int cb = jt * 64;
        const int idx = jt - jt0;
        const int buf = idx & 1;
        if (jt < jt1) issue_stage(jt + 1, buf ^ 1);
        MBAR_WAIT(mb + buf * 8, (idx >> 1) & 1);
        const char* st = smc + buf * 32768;

        // ---- S = Q K^T (tf32, LDS.64, swizzled) ----
        float sacc[2][8][4];
#pragma unroll
        for (int s2 = 0; s2 < 2; ++s2)
#pragma unroll
            for (int j = 0; j < 8; ++j)
#pragma unroll
                for (int e = 0; e < 4; ++e) sacc[s2][j][e] = 0.f;

#pragma unroll
        for (int ks = 0; ks < 8; ++ks) {
            const int f2i = (ks * 4 + q) ^ ((g & 3) << 2);
#pragma unroll
            for (int j = 0; j < 8; ++j) {
                const float2* kr = (const float2*)(st + (j * 8 + g) * 256);
                float2 b = kr[f2i];
                uint32_t b0 = __float_as_uint(b.x), b1 = __float_as_uint(b.y);
                mma1688t(sacc[0][j], qf[ks][0][0], qf[ks][0][1],
                         qf[ks][0][2], qf[ks][0][3], b0, b1);
                mma1688t(sacc[1][j], qf[ks][1][0], qf[ks][1][1],
                         qf[ks][1][2], qf[ks][1][3], b0, b1);
            }
        }

        // ---- mask + exp (in place: sacc becomes PV A-frags) ----
        const bool needMask = (jt >= 2 * it);
#pragma unroll
        for (int s2 = 0; s2 < 2; ++s2) {
            const int rg = (s2 == 0) ? rgs0 : rgs1;
#pragma unroll
            for (int j = 0; j < 8; ++j) {
                float e0 = sacc[s2][j][0], e1 = sacc[s2][j][1];
                float e2 = sacc[s2][j][2], e3 = sacc[s2][j][3];
                if (needMask) {
                    int c0 = cb + j * 8 + q * 2, c1 = c0 + 1;
                    if (c0 > rg) e0 = -1e30f;
                    if (c1 > rg) e1 = -1e30f;
                    if (c0 > rg + 8) e2 = -1e30f;
                    if (c1 > rg + 8) e3 = -1e30f;
                }
                float p0 = ex2f_fast(e0), p1 = ex2f_fast(e1);
                float p2 = ex2f_fast(e2), p3 = ex2f_fast(e3);
                lacc[s2][0] += p0 + p1;
                lacc[s2][1] += p2 + p3;
                sacc[s2][j][0] = __uint_as_float(to_tf32(p0));
                sacc[s2][j][1] = __uint_as_float(to_tf32(p2));
                sacc[s2][j][2] = __uint_as_float(to_tf32(p1));
                sacc[s2][j][3] = __uint_as_float(to_tf32(p3));
            }
        }

        // ---- O += P V (tf32; V swizzled) ----
        const char* vb = st + 16384;
#pragma unroll
        for (int ks = 0; ks < 8; ++ks) {
            const int f2i = (ks * 4 + q) ^ ((g & 3) << 2);
#pragma unroll
            for (int j = 0; j < 8; ++j) {
                const float2* vr = (const float2*)(vb + (j * 8 + g) * 256);
                float2 b = vr[f2i];
                uint32_t b0 = __float_as_uint(b.x), b1 = __float_as_uint(b.y);
                mma1688t(o[0][j],
                         __float_as_uint(sacc[0][ks][0]), __float_as_uint(sacc[0][ks][1]),
                         __float_as_uint(sacc[0][ks][2]), __float_as_uint(sacc[0][ks][3]),
                         b0, b1);
                mma1688t(o[1][j],
                         __float_as_uint(sacc[1][ks][0]), __float_as_uint(sacc[1][ks][1]),
                         __float_as_uint(sacc[1][ks][2]), __float_as_uint(sacc[1][ks][3]),
                         b0, b1);
            }
        }
        __syncthreads();   // all reads of buf done before it is refilled
    }

    // ---- reduce l, normalize, store ----
#pragma unroll
    for (int s2 = 0; s2 < 2; ++s2) {
#pragma unroll
        for (int e = 0; e < 2; ++e) {
            lacc[s2][e] += __shfl_xor_sync(0xffffffffu, lacc[s2][e], 1, 4);
            lacc[s2][e] += __shfl_xor_sync(0xffffffffu, lacc[s2][e], 2, 4);
        }
    }
#pragma unroll
    for (int s2 = 0; s2 < 2; ++s2) {
        const int rg = (s2 == 0) ? rgs0 : rgs1;
        const float inv0 = 1.0f / lacc[s2][0], inv1 = 1.0f / lacc[s2][1];
        float* og = out + ((size_t)h * T_TOT + rg) * 64;
#pragma unroll
        for (int j = 0; j < 8; ++j) {
            int c = j * 8 + q * 2;
            *(float2*)(og + c) =
                make_float2(o[s2][j][0] * inv0, o[s2][j][1] * inv0);
            *(float2*)(og + 8 * 64 + c) =
                make_float2(o[s2][j][2] * inv1, o[s2][j][3] * inv1);
        }
    }
}

// ---------------------------------------------------------------------------
extern "C" void kernel_launch(void* const* d_in, const int* in_sizes, int n_in,
                              void* d_out, int out_size)
{
    (void)in_sizes; (void)n_in; (void)out_size;
    const float* x   = (const float*)d_in[0];
    const float* Wq  = (const float*)d_in[1];
    const float* Wk  = (const float*)d_in[2];
    const float* Wv  = (const float*)d_in[3];
    const float* Wqs = (const float*)d_in[4];
    const float* Wks = (const float*)d_in[5];
    const float* Wvs = (const float*)d_in[6];
    const float* sf  = (const float*)d_in[7];
    float* out = (float*)d_out;

    cudaFuncSetAttribute(proj_kernel,
                         cudaFuncAttributeMaxDynamicSharedMemorySize, PROJ_SMEM);
    cudaFuncSetAttribute(attn_kernel,
                         cudaFuncAttributeMaxDynamicSharedMemorySize, ATTN_SMEM);

    conv_kernel<<<528, 256>>>(x, Wq, Wk, Wv, Wqs, Wks, Wvs);
    proj_kernel<<<dim3(16, 18), 512, PROJ_SMEM>>>(sf);
    attn_kernel<<<288, 128, ATTN_SMEM>>>(out);
}

// round 10
// speedup vs baseline: 1.0324x; 1.0324x over previous
#include <cuda_runtime.h>
#include <cuda_bf16.h>
#include <math.h>
#include <cstdint>

// ---------------------------------------------------------------------------
// StatefulCausalAttention  (B=1, H=16, T=2304=128+2048+128, D=1024, dk=dv=64)
// R10: attention reverted to R8 (known-profiled best). Projection re-blocked
//      to 64-row x 192-col CTAs (256 thr, warp tile m32xn48 unchanged),
//      2-stage cp.async ring, 2 CTAs/SM for latency hiding.
// ---------------------------------------------------------------------------

#define T_TOT 2304
#define D_IN  1024
#define NH    16

// projection outputs
__device__ float g_Qf[NH * T_TOT * 64];   // tf32-rounded, * sf * log2e
__device__ float g_Kf[NH * T_TOT * 64];   // tf32-rounded
__device__ float g_VTf[NH * 64 * T_TOT];  // [h][dv][t] tf32-rounded (natural)

// frag-shuffled tf32 operands for projection
__device__ float g_Xf[144 * 64 * 2 * 32 * 4];
__device__ float g_Wf[6 * 16 * 64 * 8 * 32 * 4];

// ============================ helpers ======================================
__device__ __forceinline__ float ex2f_fast(float x) {
    float y; asm("ex2.approx.f32 %0, %1;" : "=f"(y) : "f"(x)); return y;
}
__device__ __forceinline__ void mma1688t(float* c, uint32_t a0, uint32_t a1,
                                         uint32_t a2, uint32_t a3,
                                         uint32_t b0, uint32_t b1) {
    asm("mma.sync.aligned.m16n8k8.row.col.f32.tf32.tf32.f32 "
        "{%0,%1,%2,%3}, {%4,%5,%6,%7}, {%8,%9}, {%0,%1,%2,%3};"
        : "+f"(c[0]), "+f"(c[1]), "+f"(c[2]), "+f"(c[3])
        : "r"(a0), "r"(a1), "r"(a2), "r"(a3), "r"(b0), "r"(b1));
}
__device__ __forceinline__ uint32_t to_tf32(float f) {
    uint32_t u; asm("cvt.rna.tf32.f32 %0, %1;" : "=r"(u) : "f"(f)); return u;
}
__device__ __forceinline__ uint32_t smem_u32(const void* p) {
    uint32_t a;
    asm("{ .reg .u64 t; cvta.to.shared.u64 t, %1; cvt.u32.u64 %0, t; }" : "=r"(a) : "l"(p));
    return a;
}
#define CP_ASYNC16(dst, src) \
    asm volatile("cp.async.cg.shared.global [%0], [%1], 16;" :: "r"(dst), "l"(src))
#define CP_COMMIT() asm volatile("cp.async.commit_group;" ::: "memory")
#define CP_WAIT(n)  asm volatile("cp.async.wait_group %0;" :: "n"(n) : "memory")

// ============================ prep: X + W -> frag order (merged) ===========
__global__ __launch_bounds__(256) void conv_kernel(
    const float* __restrict__ x,
    const float* __restrict__ Wq,  const float* __restrict__ Wk,  const float* __restrict__ Wv,
    const float* __restrict__ Wqs, const float* __restrict__ Wks, const float* __restrict__ Wvs)
{
    const int bid = blockIdx.x;
    if (bid < 144) {
        const int strip = bid;
        for (int i = threadIdx.x; i < 4096; i += 256) {
            int c = i >> 6, rest = i & 63;
            int t = rest >> 5, ln = rest & 31;
            int g = ln >> 2, q = ln & 3;
            const float* xr = x + (size_t)(strip * 16 + t * 8 + g) * D_IN + c * 16;
            uint4 v;
            v.x = to_tf32(xr[q]);
            v.y = to_tf32(xr[8 + q]);
            v.z = to_tf32(xr[4 + q]);
            v.w = to_tf32(xr[12 + q]);
            ((uint4*)g_Xf)[(size_t)(strip * 64 + c) * 64 + rest] = v;
        }
    } else {
        const int wb = bid - 144;          // 0..383
        const int cb = (wb & 3) * 16;
        const int mh = wb >> 2;            // 0..95
        const int mat = mh >> 4, h = mh & 15;
        const float* W;
        switch (mat) {
            case 0: W = Wq;  break; case 1: W = Wqs; break;
            case 2: W = Wk;  break; case 3: W = Wks; break;
            case 4: W = Wv;  break; default: W = Wvs; break;
        }
        W += (size_t)h * D_IN * 64;
        const int tid = threadIdx.x;
        const int ntl = tid >> 5, ln = tid & 31;
        const int g = ln >> 2, r = ln & 3;
        const int n = ntl * 8 + g;
#pragma unroll 4
        for (int ci = 0; ci < 16; ++ci) {
            const int c = cb + ci, k0 = c * 16;
            uint4 v;
            v.x = to_tf32(W[(size_t)(k0 + r) * 64 + n]);
            v.y = to_tf32(W[(size_t)(k0 + 8 + r) * 64 + n]);
            v.z = to_tf32(W[(size_t)(k0 + 4 + r) * 64 + n]);
            v.w = to_tf32(W[(size_t)(k0 + 12 + r) * 64 + n]);
            ((uint4*)g_Wf)[((size_t)(mat * 16 + h) * 64 + c) * 256 + tid] = v;
        }
    }
}

// ============================ projection v3 (tf32 mma, 256 thr, 2 CTA/SM) ==
// block (h, by): rows by*64..+63, q,k,v fused (N=192). 8 warps:
// mi = warp>>2 (m32 = 2 strips of 16), ni = warp&3 (n48). 2-stage cp.async.
// stage s at s*16384: A 256 uint4 (4KB), B 768 uint4 (12KB);
// nrm[3][64] floats at 32768.
#define PROJ_SMEM (32768 + 768)

__global__ __launch_bounds__(256, 2) void proj_kernel(const float* __restrict__ sf)
{
    extern __shared__ char smc[];
    float* nrm = (float*)(smc + 32768);
    const uint32_t sb = smem_u32(smc);
    const int h  = blockIdx.x;
    const int by = blockIdx.y;                 // 0..35 (64-row tiles)
    const int state = (by < 2 || by >= 34) ? 1 : 0;
    const int tid = threadIdx.x, warp = tid >> 5, lane = tid & 31;
    const int mi = warp >> 2, ni = warp & 3;
    const int g = lane >> 2, qq = lane & 3;
    const int strip0 = by * 4;

    for (int i = tid; i < 192; i += 256) nrm[i] = 0.f;
    __syncthreads();

    float acc[2][6][4];
#pragma unroll
    for (int st = 0; st < 2; ++st)
#pragma unroll
        for (int nt = 0; nt < 6; ++nt)
#pragma unroll
            for (int e = 0; e < 4; ++e) acc[st][nt][e] = 0.f;

    auto issue_stage = [&](int c) {
        const uint32_t sa = sb + (c & 1) * 16384;
#pragma unroll
        for (int i = 0; i < 4; ++i) {
            int slot = tid + i * 256;
            if (slot < 256) {
                const float* src = g_Xf + ((size_t)((strip0 + (slot >> 6)) * 64 + c) * 64
                                           + (slot & 63)) * 4;
                CP_ASYNC16(sa + slot * 16, src);
            } else {
                int s2 = slot - 256;
                int mat = (s2 >> 8) * 2 + state;
                const float* src = g_Wf + (((size_t)(mat * 16 + h) * 64 + c) * 256
                                           + (s2 & 255)) * 4;
                CP_ASYNC16(sa + 4096 + s2 * 16, src);
            }
        }
    };

    issue_stage(0); CP_COMMIT();

    for (int c = 0; c < 64; ++c) {
        if (c + 1 < 64) { issue_stage(c + 1); CP_COMMIT(); CP_WAIT(1); }
        else            { CP_WAIT(0); }
        __syncthreads();

        const char* sa = smc + (c & 1) * 16384;
        uint4 Af[2][2], Bf[6];
#pragma unroll
        for (int st = 0; st < 2; ++st)
#pragma unroll
            for (int t = 0; t < 2; ++t)
                Af[st][t] = *(const uint4*)(sa + (((mi * 2 + st) * 2 + t) * 32 + lane) * 16);
#pragma unroll
        for (int nt = 0; nt < 6; ++nt)
            Bf[nt] = *(const uint4*)(sa + 4096 + ((ni * 6 + nt) * 32 + lane) * 16);

#pragma unroll
        for (int s = 0; s < 2; ++s) {
#pragma unroll
            for (int st = 0; st < 2; ++st) {
                uint32_t a0 = s ? Af[st][0].y : Af[st][0].x;
                uint32_t a1 = s ? Af[st][1].y : Af[st][1].x;
                uint32_t a2 = s ? Af[st][0].w : Af[st][0].z;
                uint32_t a3 = s ? Af[st][1].w : Af[st][1].z;
#pragma unroll
                for (int nt = 0; nt < 6; ++nt) {
                    uint32_t b0 = s ? Bf[nt].y : Bf[nt].x;
                    uint32_t b1 = s ? Bf[nt].w : Bf[nt].z;
                    mma1688t(acc[st][nt], a0, a1, a2, a3, b0, b1);
                }
            }
        }
        __syncthreads();
    }

    // ---- norm partials (rows x mats = 64 x 3) ----
#pragma unroll
    for (int st = 0; st < 2; ++st) {
#pragma unroll
        for (int nt = 0; nt < 6; ++nt) {
            int mat = (ni * 6 + nt) >> 3;
            int rl0 = (mi * 2 + st) * 16 + g;
            atomicAdd(&nrm[mat * 64 + rl0],
                      acc[st][nt][0] * acc[st][nt][0] + acc[st][nt][1] * acc[st][nt][1]);
            atomicAdd(&nrm[mat * 64 + rl0 + 8],
                      acc[st][nt][2] * acc[st][nt][2] + acc[st][nt][3] * acc[st][nt][3]);
        }
    }
    __syncthreads();

    // ---- scale + store: Q/K tf32 fp32; V tf32 fp32 transposed (natural) ----
    const float qs = sf[h] * 1.44269504088896340736f;
#pragma unroll
    for (int st = 0; st < 2; ++st) {
        const int rl0 = (mi * 2 + st) * 16 + g;
        const int rg0 = by * 64 + rl0;
#pragma unroll
        for (int nt = 0; nt < 6; ++nt) {
            const int ntg = ni * 6 + nt;
            const int mat = ntg >> 3;
            const int ntl = ntg & 7;
            const float mult = (mat == 0) ? qs : 1.0f;
            float inv0 = mult / fmaxf(sqrtf(nrm[mat * 64 + rl0]),     1e-12f);
            float inv1 = mult / fmaxf(sqrtf(nrm[mat * 64 + rl0 + 8]), 1e-12f);
            float v0 = acc[st][nt][0] * inv0, v1 = acc[st][nt][1] * inv0;
            float v2 = acc[st][nt][2] * inv1, v3 = acc[st][nt][3] * inv1;
            const int col = ntl * 8 + qq * 2;
            if (mat < 2) {
                float* dst = (mat == 0 ? g_Qf : g_Kf) + (size_t)h * T_TOT * 64;
                *(uint2*)(dst + (size_t)(rg0    ) * 64 + col) =
                    make_uint2(to_tf32(v0), to_tf32(v1));
                *(uint2*)(dst + (size_t)(rg0 + 8) * 64 + col) =
                    make_uint2(to_tf32(v2), to_tf32(v3));
            } else {
                float* dv = g_VTf + (size_t)h * 64 * T_TOT;
                float vv[4] = {v0, v1, v2, v3};
#pragma unroll
                for (int e = 0; e < 4; ++e) {
                    int cc = col + (e & 1);
                    int rr = rg0 + (e >> 1) * 8;
                    dv[(size_t)cc * T_TOT + rr] = __uint_as_float(to_tf32(vv[e]));
                }
            }
        }
    }
}

// ============================ attention (R8 version) =======================
// 256 threads, 8 warps x 16 q-rows, kv-tile 64, 2 CTAs/SM, snake schedule.
// LDS.64 B-frags via contraction relabel; 288B row stride (conflict-free).
// Stage (36864 B): K f32 [64 rows][288B] @0 ; V f32 [64 dv][288B] @18432.
#define STAGE_B 36864
#define ATTN_SMEM (2 * STAGE_B)

__global__ __launch_bounds__(256, 2) void attn_kernel(float* __restrict__ out)
{
    extern __shared__ char smc[];
    const uint32_t sb = smem_u32(smc);
    const int L = blockIdx.x;
    const int r = (L < 152) ? L : 439 - L;
    const int h  = r & 15;
    const int it = 17 - (r >> 4);
    const int rb = it * 128;
    const int tid = threadIdx.x;
    const int warp = tid >> 5, lane = tid & 31;
    const int g = lane >> 2, q = lane & 3;
    const int rg0 = rb + warp * 16 + g;

    // ---- Q fragments: k-lane q <-> logical k = 2q, 2q+1 ----
    uint32_t qf[8][4];
    {
        const float* Qf = g_Qf + ((size_t)h * T_TOT + rg0) * 64;
#pragma unroll
        for (int ks = 0; ks < 8; ++ks) {
            float2 lo = *(const float2*)&Qf[ks * 8 + 2 * q];
            float2 hi = *(const float2*)&Qf[8 * 64 + ks * 8 + 2 * q];
            qf[ks][0] = __float_as_uint(lo.x);
            qf[ks][1] = __float_as_uint(hi.x);
            qf[ks][2] = __float_as_uint(lo.y);
            qf[ks][3] = __float_as_uint(hi.y);
        }
    }

    float o[8][4];
#pragma unroll
    for (int j = 0; j < 8; ++j)
#pragma unroll
        for (int e = 0; e < 4; ++e) o[j][e] = 0.f;
    float l0 = 0.f, l1 = 0.f;

    const int jt0 = (it == 17) ? 2 : 0;
    const int jt1 = 2 * it + 1;

    auto issue_stage = [&](int jt, int buf) {
        const int cb = jt * 64;
        const uint32_t stb = sb + buf * STAGE_B;
#pragma unroll
        for (int i = 0; i < 8; ++i) {
            int slot = tid + i * 256;
            int arr = slot >> 10;              // 0=K 1=V
            int s2 = slot & 1023;
            int row = s2 >> 4, ch = s2 & 15;
            const float* src = (arr == 0)
                ? g_Kf  + ((size_t)h * T_TOT + cb + row) * 64 + ch * 4
                : g_VTf + (size_t)h * 64 * T_TOT + (size_t)row * T_TOT + cb + ch * 4;
            CP_ASYNC16(stb + arr * 18432 + row * 288 + ch * 16, src);
        }
    };

    issue_stage(jt0, 0);
    CP_COMMIT();

    for (int jt = jt0; jt <= jt1; ++jt) {
        const int cb = jt * 64;
        const int buf = (jt - jt0) & 1;
        const char* st = smc + buf * STAGE_B;

        if (jt < jt1) { issue_stage(jt + 1, buf ^ 1); CP_COMMIT(); CP_WAIT(1); }
        else          { CP_WAIT(0); }
        __syncthreads();

        // ---- S = Q K^T (tf32, LDS.64 B-frags) ----
        float sacc[8][4];
#pragma unroll
        for (int j = 0; j < 8; ++j)
#pragma unroll
            for (int e = 0; e < 4; ++e) sacc[j][e] = 0.f;

#pragma unroll
        for (int ks = 0; ks < 8; ++ks) {
#pragma unroll
            for (int j = 0; j < 8; ++j) {
                const float2* kr = (const float2*)(st + (j * 8 + g) * 288);
                float2 b = kr[ks * 4 + q];
                mma1688t(sacc[j], qf[ks][0], qf[ks][1], qf[ks][2], qf[ks][3],
                         __float_as_uint(b.x), __float_as_uint(b.y));
            }
        }

        // ---- mask + exp (sacc layout = PV A-frag layout under relabel) ----
        const bool needMask = (jt >= 2 * it);
        uint32_t pa[8][4];
#pragma unroll
        for (int j = 0; j < 8; ++j) {
            float e0 = sacc[j][0], e1 = sacc[j][1];
            float e2 = sacc[j][2], e3 = sacc[j][3];
            if (needMask) {
                int c0 = cb + j * 8 + q * 2, c1 = c0 + 1;
                if (c0 > rg0) e0 = -1e30f;
                if (c1 > rg0) e1 = -1e30f;
                if (c0 > rg0 + 8) e2 = -1e30f;
                if (c1 > rg0 + 8) e3 = -1e30f;
            }
            float p0 = ex2f_fast(e0), p1 = ex2f_fast(e1);
            float p2 = ex2f_fast(e2), p3 = ex2f_fast(e3);
            l0 += p0 + p1;
            l1 += p2 + p3;
            pa[j][0] = to_tf32(p0);
            pa[j][1] = to_tf32(p2);
            pa[j][2] = to_tf32(p1);
            pa[j][3] = to_tf32(p3);
        }

        // ---- O += P V (tf32; V natural order, LDS.64 B-frags) ----
        const char* vb = st + 18432;
#pragma unroll
        for (int ks = 0; ks < 8; ++ks) {
#pragma unroll
            for (int j = 0; j < 8; ++j) {
                const float2* vr = (const float2*)(vb + (j * 8 + g) * 288);
                float2 b = vr[ks * 4 + q];
                mma1688t(o[j], pa[ks][0], pa[ks][1], pa[ks][2], pa[ks][3],
                         __float_as_uint(b.x), __float_as_uint(b.y));
            }
        }
        __syncthreads();   // all reads of buf done before refill
    }

    // ---- reduce l, normalize, store ----
    l0 += __shfl_xor_sync(0xffffffffu, l0, 1, 4);
    l0 += __shfl_xor_sync(0xffffffffu, l0, 2, 4);
    l1 += __shfl_xor_sync(0xffffffffu, l1, 1, 4);
    l1 += __shfl_xor_sync(0xffffffffu, l1, 2, 4);
    const float inv0 = 1.0f / l0, inv1 = 1.0f / l1;

    float* og = out + ((size_t)h * T_TOT + rg0) * 64;
#pragma unroll
    for (int j = 0; j < 8; ++j) {
        int c = j * 8 + q * 2;
        *(float2*)(og + c)          = make_float2(o[j][0] * inv0, o[j][1] * inv0);
        *(float2*)(og + 8 * 64 + c) = make_float2(o[j][2] * inv1, o[j][3] * inv1);
    }
}

// ---------------------------------------------------------------------------
extern "C" void kernel_launch(void* const* d_in, const int* in_sizes, int n_in,
                              void* d_out, int out_size)
{
    (void)in_sizes; (void)n_in; (void)out_size;
    const float* x   = (const float*)d_in[0];
    const float* Wq  = (const float*)d_in[1];
    const float* Wk  = (const float*)d_in[2];
    const float* Wv  = (const float*)d_in[3];
    const float* Wqs = (const float*)d_in[4];
    const float* Wks = (const float*)d_in[5];
    const float* Wvs = (const float*)d_in[6];
    const float* sf  = (const float*)d_in[7];
    float* out = (float*)d_out;

    cudaFuncSetAttribute(proj_kernel,
                         cudaFuncAttributeMaxDynamicSharedMemorySize, PROJ_SMEM);
    cudaFuncSetAttribute(attn_kernel,
                         cudaFuncAttributeMaxDynamicSharedMemorySize, ATTN_SMEM);

    conv_kernel<<<528, 256>>>(x, Wq, Wk, Wv, Wqs, Wks, Wvs);
    proj_kernel<<<dim3(16, 36), 256, PROJ_SMEM>>>(sf);
    attn_kernel<<<288, 256, ATTN_SMEM>>>(out);
}

// round 11
// speedup vs baseline: 1.0413x; 1.0086x over previous
#include <cuda_runtime.h>
#include <cuda_bf16.h>
#include <math.h>
#include <cstdint>

// ---------------------------------------------------------------------------
// StatefulCausalAttention  (B=1, H=16, T=2304=128+2048+128, D=1024, dk=dv=64)
// R11: attn software-pipelined (PV(jt) -> S(jt+1) -> exp(jt+1)), 3-stage ring,
//      one sync per tile, pa reuses sacc registers in place.
//      conv re-gridded 528 -> 2112 blocks (latency hiding).
//      proj unchanged from R10.
// ---------------------------------------------------------------------------

#define T_TOT 2304
#define D_IN  1024
#define NH    16

// projection outputs
__device__ float g_Qf[NH * T_TOT * 64];   // tf32-rounded, * sf * log2e
__device__ float g_Kf[NH * T_TOT * 64];   // tf32-rounded
__device__ float g_VTf[NH * 64 * T_TOT];  // [h][dv][t] tf32-rounded (natural)

// frag-shuffled tf32 operands for projection
__device__ float g_Xf[144 * 64 * 2 * 32 * 4];
__device__ float g_Wf[6 * 16 * 64 * 8 * 32 * 4];

// ============================ helpers ======================================
__device__ __forceinline__ float ex2f_fast(float x) {
    float y; asm("ex2.approx.f32 %0, %1;" : "=f"(y) : "f"(x)); return y;
}
__device__ __forceinline__ void mma1688t(float* c, uint32_t a0, uint32_t a1,
                                         uint32_t a2, uint32_t a3,
                                         uint32_t b0, uint32_t b1) {
    asm("mma.sync.aligned.m16n8k8.row.col.f32.tf32.tf32.f32 "
        "{%0,%1,%2,%3}, {%4,%5,%6,%7}, {%8,%9}, {%0,%1,%2,%3};"
        : "+f"(c[0]), "+f"(c[1]), "+f"(c[2]), "+f"(c[3])
        : "r"(a0), "r"(a1), "r"(a2), "r"(a3), "r"(b0), "r"(b1));
}
__device__ __forceinline__ uint32_t to_tf32(float f) {
    uint32_t u; asm("cvt.rna.tf32.f32 %0, %1;" : "=r"(u) : "f"(f)); return u;
}
__device__ __forceinline__ uint32_t smem_u32(const void* p) {
    uint32_t a;
    asm("{ .reg .u64 t; cvta.to.shared.u64 t, %1; cvt.u32.u64 %0, t; }" : "=r"(a) : "l"(p));
    return a;
}
#define CP_ASYNC16(dst, src) \
    asm volatile("cp.async.cg.shared.global [%0], [%1], 16;" :: "r"(dst), "l"(src))
#define CP_COMMIT() asm volatile("cp.async.commit_group;" ::: "memory")
#define CP_WAIT(n)  asm volatile("cp.async.wait_group %0;" :: "n"(n) : "memory")

// ============================ prep: X + W -> frag order (merged, fine grid) =
__global__ __launch_bounds__(256) void conv_kernel(
    const float* __restrict__ x,
    const float* __restrict__ Wq,  const float* __restrict__ Wk,  const float* __restrict__ Wv,
    const float* __restrict__ Wqs, const float* __restrict__ Wks, const float* __restrict__ Wvs)
{
    const int bid = blockIdx.x;
    const int tid = threadIdx.x;
    if (bid < 576) {
        // X: 589824 items total, 1024 per block
#pragma unroll
        for (int p = 0; p < 4; ++p) {
            int idx = bid * 1024 + p * 256 + tid;
            int strip = idx >> 12;
            int i = idx & 4095;
            int c = i >> 6, rest = i & 63;
            int t = rest >> 5, ln = rest & 31;
            int g = ln >> 2, q = ln & 3;
            const float* xr = x + (size_t)(strip * 16 + t * 8 + g) * D_IN + c * 16;
            uint4 v;
            v.x = to_tf32(xr[q]);
            v.y = to_tf32(xr[8 + q]);
            v.z = to_tf32(xr[4 + q]);
            v.w = to_tf32(xr[12 + q]);
            ((uint4*)g_Xf)[(size_t)(strip * 64 + c) * 64 + rest] = v;
        }
    } else {
        const int wb = bid - 576;          // 0..1535
        const int mh = wb >> 4;            // 0..95
        const int cg = wb & 15;            // group of 4 chunks
        const int mat = mh >> 4, h = mh & 15;
        const float* W;
        switch (mat) {
            case 0: W = Wq;  break; case 1: W = Wqs; break;
            case 2: W = Wk;  break; case 3: W = Wks; break;
            case 4: W = Wv;  break; default: W = Wvs; break;
        }
        W += (size_t)h * D_IN * 64;
        const int ntl = tid >> 5, ln = tid & 31;
        const int g = ln >> 2, r = ln & 3;
        const int n = ntl * 8 + g;
#pragma unroll
        for (int ci = 0; ci < 4; ++ci) {
            const int c = cg * 4 + ci, k0 = c * 16;
            uint4 v;
            v.x = to_tf32(W[(size_t)(k0 + r) * 64 + n]);
            v.y = to_tf32(W[(size_t)(k0 + 8 + r) * 64 + n]);
            v.z = to_tf32(W[(size_t)(k0 + 4 + r) * 64 + n]);
            v.w = to_tf32(W[(size_t)(k0 + 12 + r) * 64 + n]);
            ((uint4*)g_Wf)[((size_t)(mat * 16 + h) * 64 + c) * 256 + tid] = v;
        }
    }
}

// ============================ projection (tf32 mma, 256 thr, 2 CTA/SM) =====
// (unchanged from R10)
#define PROJ_SMEM (32768 + 768)

__global__ __launch_bounds__(256, 2) void proj_kernel(const float* __restrict__ sf)
{
    extern __shared__ char smc[];
    float* nrm = (float*)(smc + 32768);
    const uint32_t sb = smem_u32(smc);
    const int h  = blockIdx.x;
    const int by = blockIdx.y;                 // 0..35 (64-row tiles)
    const int state = (by < 2 || by >= 34) ? 1 : 0;
    const int tid = threadIdx.x, warp = tid >> 5, lane = tid & 31;
    const int mi = warp >> 2, ni = warp & 3;
    const int g = lane >> 2, qq = lane & 3;
    const int strip0 = by * 4;

    for (int i = tid; i < 192; i += 256) nrm[i] = 0.f;
    __syncthreads();

    float acc[2][6][4];
#pragma unroll
    for (int st = 0; st < 2; ++st)
#pragma unroll
        for (int nt = 0; nt < 6; ++nt)
#pragma unroll
            for (int e = 0; e < 4; ++e) acc[st][nt][e] = 0.f;

    auto issue_stage = [&](int c) {
        const uint32_t sa = sb + (c & 1) * 16384;
#pragma unroll
        for (int i = 0; i < 4; ++i) {
            int slot = tid + i * 256;
            if (slot < 256) {
                const float* src = g_Xf + ((size_t)((strip0 + (slot >> 6)) * 64 + c) * 64
                                           + (slot & 63)) * 4;
                CP_ASYNC16(sa + slot * 16, src);
            } else {
                int s2 = slot - 256;
                int mat = (s2 >> 8) * 2 + state;
                const float* src = g_Wf + (((size_t)(mat * 16 + h) * 64 + c) * 256
                                           + (s2 & 255)) * 4;
                CP_ASYNC16(sa + 4096 + s2 * 16, src);
            }
        }
    };

    issue_stage(0); CP_COMMIT();

    for (int c = 0; c < 64; ++c) {
        if (c + 1 < 64) { issue_stage(c + 1); CP_COMMIT(); CP_WAIT(1); }
        else            { CP_WAIT(0); }
        __syncthreads();

        const char* sa = smc + (c & 1) * 16384;
        uint4 Af[2][2], Bf[6];
#pragma unroll
        for (int st = 0; st < 2; ++st)
#pragma unroll
            for (int t = 0; t < 2; ++t)
                Af[st][t] = *(const uint4*)(sa + (((mi * 2 + st) * 2 + t) * 32 + lane) * 16);
#pragma unroll
        for (int nt = 0; nt < 6; ++nt)
            Bf[nt] = *(const uint4*)(sa + 4096 + ((ni * 6 + nt) * 32 + lane) * 16);

#pragma unroll
        for (int s = 0; s < 2; ++s) {
#pragma unroll
            for (int st = 0; st < 2; ++st) {
                uint32_t a0 = s ? Af[st][0].y : Af[st][0].x;
                uint32_t a1 = s ? Af[st][1].y : Af[st][1].x;
                uint32_t a2 = s ? Af[st][0].w : Af[st][0].z;
                uint32_t a3 = s ? Af[st][1].w : Af[st][1].z;
#pragma unroll
                for (int nt = 0; nt < 6; ++nt) {
                    uint32_t b0 = s ? Bf[nt].y : Bf[nt].x;
                    uint32_t b1 = s ? Bf[nt].w : Bf[nt].z;
                    mma1688t(acc[st][nt], a0, a1, a2, a3, b0, b1);
                }
            }
        }
        __syncthreads();
    }

    // ---- norm partials ----
#pragma unroll
    for (int st = 0; st < 2; ++st) {
#pragma unroll
        for (int nt = 0; nt < 6; ++nt) {
            int mat = (ni * 6 + nt) >> 3;
            int rl0 = (mi * 2 + st) * 16 + g;
            atomicAdd(&nrm[mat * 64 + rl0],
                      acc[st][nt][0] * acc[st][nt][0] + acc[st][nt][1] * acc[st][nt][1]);
            atomicAdd(&nrm[mat * 64 + rl0 + 8],
                      acc[st][nt][2] * acc[st][nt][2] + acc[st][nt][3] * acc[st][nt][3]);
        }
    }
    __syncthreads();

    // ---- scale + store ----
    const float qs = sf[h] * 1.44269504088896340736f;
#pragma unroll
    for (int st = 0; st < 2; ++st) {
        const int rl0 = (mi * 2 + st) * 16 + g;
        const int rg0 = by * 64 + rl0;
#pragma unroll
        for (int nt = 0; nt < 6; ++nt) {
            const int ntg = ni * 6 + nt;
            const int mat = ntg >> 3;
            const int ntl = ntg & 7;
            const float mult = (mat == 0) ? qs : 1.0f;
            float inv0 = mult / fmaxf(sqrtf(nrm[mat * 64 + rl0]),     1e-12f);
            float inv1 = mult / fmaxf(sqrtf(nrm[mat * 64 + rl0 + 8]), 1e-12f);
            float v0 = acc[st][nt][0] * inv0, v1 = acc[st][nt][1] * inv0;
            float v2 = acc[st][nt][2] * inv1, v3 = acc[st][nt][3] * inv1;
            const int col = ntl * 8 + qq * 2;
            if (mat < 2) {
                float* dst = (mat == 0 ? g_Qf : g_Kf) + (size_t)h * T_TOT * 64;
                *(uint2*)(dst + (size_t)(rg0    ) * 64 + col) =
                    make_uint2(to_tf32(v0), to_tf32(v1));
                *(uint2*)(dst + (size_t)(rg0 + 8) * 64 + col) =
                    make_uint2(to_tf32(v2), to_tf32(v3));
            } else {
                float* dv = g_VTf + (size_t)h * 64 * T_TOT;
                float vv[4] = {v0, v1, v2, v3};
#pragma unroll
                for (int e = 0; e < 4; ++e) {
                    int cc = col + (e & 1);
                    int rr = rg0 + (e >> 1) * 8;
                    dv[(size_t)cc * T_TOT + rr] = __uint_as_float(to_tf32(vv[e]));
                }
            }
        }
    }
}

// ============================ attention v6 (pipelined) =====================
// 256 threads, 8 warps x 16 q-rows, kv-tile 64, 2 CTAs/SM, snake schedule.
// 3-stage ring; loop order PV(jt) -> [wait+sync] -> S(jt+1) -> exp(jt+1).
// ps[] doubles as S accumulator and P A-fragments (in-place exp).
// Stage (36864 B): K f32 [64 rows][288B] @0 ; V f32 [64 dv][288B] @18432.
#define STAGE_B 36864
#define ATTN_SMEM (3 * STAGE_B)

__global__ __launch_bounds__(256, 2) void attn_kernel(float* __restrict__ out)
{
    extern __shared__ char smc[];
    const uint32_t sb = smem_u32(smc);
    const int L = blockIdx.x;
    const int r = (L < 152) ? L : 439 - L;
    const int h  = r & 15;
    const int it = 17 - (r >> 4);
    const int rb = it * 128;
    const int tid = threadIdx.x;
    const int warp = tid >> 5, lane = tid & 31;
    const int g = lane >> 2, q = lane & 3;
    const int rg0 = rb + warp * 16 + g;

    // ---- Q fragments: k-lane q <-> logical k = 2q, 2q+1 ----
    uint32_t qf[8][4];
    {
        const float* Qf = g_Qf + ((size_t)h * T_TOT + rg0) * 64;
#pragma unroll
        for (int ks = 0; ks < 8; ++ks) {
            float2 lo = *(const float2*)&Qf[ks * 8 + 2 * q];
            float2 hi = *(const float2*)&Qf[8 * 64 + ks * 8 + 2 * q];
            qf[ks][0] = __float_as_uint(lo.x);
            qf[ks][1] = __float_as_uint(hi.x);
            qf[ks][2] = __float_as_uint(lo.y);
            qf[ks][3] = __float_as_uint(hi.y);
        }
    }

    float o[8][4];
#pragma unroll
    for (int j = 0; j < 8; ++j)
#pragma unroll
        for (int e = 0; e < 4; ++e) o[j][e] = 0.f;
    float l0 = 0.f, l1 = 0.f;
    float ps[8][4];                       // S acc / P A-frags (in place)

    const int jt0 = (it == 17) ? 2 : 0;
    const int jt1 = 2 * it + 1;           // >= jt0 + 1 always

    auto issue_stage = [&](int jt, int buf) {
        const int cb = jt * 64;
        const uint32_t stb = sb + buf * STAGE_B;
#pragma unroll
        for (int i = 0; i < 8; ++i) {
            int slot = tid + i * 256;
            int arr = slot >> 10;              // 0=K 1=V
            int s2 = slot & 1023;
            int row = s2 >> 4, ch = s2 & 15;
            const float* src = (arr == 0)
                ? g_Kf  + ((size_t)h * T_TOT + cb + row) * 64 + ch * 4
                : g_VTf + (size_t)h * 64 * T_TOT + (size_t)row * T_TOT + cb + ch * 4;
            CP_ASYNC16(stb + arr * 18432 + row * 288 + ch * 16, src);
        }
    };

    auto do_S = [&](const char* st) {
#pragma unroll
        for (int j = 0; j < 8; ++j)
#pragma unroll
            for (int e = 0; e < 4; ++e) ps[j][e] = 0.f;
#pragma unroll
        for (int ks = 0; ks < 8; ++ks) {
#pragma unroll
            for (int j = 0; j < 8; ++j) {
                const float2* kr = (const float2*)(st + (j * 8 + g) * 288);
                float2 b = kr[ks * 4 + q];
                mma1688t(ps[j], qf[ks][0], qf[ks][1], qf[ks][2], qf[ks][3],
                         __float_as_uint(b.x), __float_as_uint(b.y));
            }
        }
    };

    auto do_exp = [&](int jt_) {
        const int cb_ = jt_ * 64;
        const bool needMask = (jt_ >= 2 * it);
#pragma unroll
        for (int j = 0; j < 8; ++j) {
            float e0 = ps[j][0], e1 = ps[j][1];
            float e2 = ps[j][2], e3 = ps[j][3];
            if (needMask) {
                int c0 = cb_ + j * 8 + q * 2, c1 = c0 + 1;
                if (c0 > rg0) e0 = -1e30f;
                if (c1 > rg0) e1 = -1e30f;
                if (c0 > rg0 + 8) e2 = -1e30f;
                if (c1 > rg0 + 8) e3 = -1e30f;
            }
            float p0 = ex2f_fast(e0), p1 = ex2f_fast(e1);
            float p2 = ex2f_fast(e2), p3 = ex2f_fast(e3);
            l0 += p0 + p1;
            l1 += p2 + p3;
            // A-frag perm: a0=p0 a1=p2 a2=p1 a3=p3 (relabel absorbs order)
            ps[j][0] = __uint_as_float(to_tf32(p0));
            ps[j][1] = __uint_as_float(to_tf32(p2));
            ps[j][2] = __uint_as_float(to_tf32(p1));
            ps[j][3] = __uint_as_float(to_tf32(p3));
        }
    };

    auto do_PV = [&](const char* st) {
        const char* vb = st + 18432;
#pragma unroll
        for (int ks = 0; ks < 8; ++ks) {
#pragma unroll
            for (int j = 0; j < 8; ++j) {
                const float2* vr = (const float2*)(vb + (j * 8 + g) * 288);
                float2 b = vr[ks * 4 + q];
                mma1688t(o[j], __float_as_uint(ps[ks][0]), __float_as_uint(ps[ks][1]),
                         __float_as_uint(ps[ks][2]), __float_as_uint(ps[ks][3]),
                         __float_as_uint(b.x), __float_as_uint(b.y));
            }
        }
    };

    // ---- prologue: load jt0, jt0+1; compute S/exp for jt0 ----
    issue_stage(jt0, 0);     CP_COMMIT();
    issue_stage(jt0 + 1, 1); CP_COMMIT();
    CP_WAIT(1);
    __syncthreads();
    do_S(smc);               // buffer 0
    do_exp(jt0);

    for (int jt = jt0; jt <= jt1; ++jt) {
        const int bufc = (jt - jt0) % 3;
        do_PV(smc + bufc * STAGE_B);
        if (jt < jt1) {
            CP_WAIT(0);
            __syncthreads();       // stage jt+1 visible; all warps past PV(jt-1)
            if (jt + 2 <= jt1) {
                issue_stage(jt + 2, (jt + 2 - jt0) % 3);
                CP_COMMIT();
            }
            do_S(smc + ((jt + 1 - jt0) % 3) * STAGE_B);
            do_exp(jt + 1);
        }
    }

    // ---- reduce l, normalize, store ----
    l0 += __shfl_xor_sync(0xffffffffu, l0, 1, 4);
    l0 += __shfl_xor_sync(0xffffffffu, l0, 2, 4);
    l1 += __shfl_xor_sync(0xffffffffu, l1, 1, 4);
    l1 += __shfl_xor_sync(0xffffffffu, l1, 2, 4);
    const float inv0 = 1.0f / l0, inv1 = 1.0f / l1;

    float* og = out + ((size_t)h * T_TOT + rg0) * 64;
#pragma unroll
    for (int j = 0; j < 8; ++j) {
        int c = j * 8 + q * 2;
        *(float2*)(og + c)          = make_float2(o[j][0] * inv0, o[j][1] * inv0);
        *(float2*)(og + 8 * 64 + c) = make_float2(o[j][2] * inv1, o[j][3] * inv1);
    }
}

// ---------------------------------------------------------------------------
extern "C" void kernel_launch(void* const* d_in, const int* in_sizes, int n_in,
                              void* d_out, int out_size)
{
    (void)in_sizes; (void)n_in; (void)out_size;
    const float* x   = (const float*)d_in[0];
    const float* Wq  = (const float*)d_in[1];
    const float* Wk  = (const float*)d_in[2];
    const float* Wv  = (const float*)d_in[3];
    const float* Wqs = (const float*)d_in[4];
    const float* Wks = (const float*)d_in[5];
    const float* Wvs = (const float*)d_in[6];
    const float* sf  = (const float*)d_in[7];
    float* out = (float*)d_out;

    cudaFuncSetAttribute(proj_kernel,
                         cudaFuncAttributeMaxDynamicSharedMemorySize, PROJ_SMEM);
    cudaFuncSetAttribute(attn_kernel,
                         cudaFuncAttributeMaxDynamicSharedMemorySize, ATTN_SMEM);

    conv_kernel<<<2112, 256>>>(x, Wq, Wk, Wv, Wqs, Wks, Wvs);
    proj_kernel<<<dim3(16, 36), 256, PROJ_SMEM>>>(sf);
    attn_kernel<<<288, 256, ATTN_SMEM>>>(out);
}